// round 1
// baseline (speedup 1.0000x reference)
#include <cuda_runtime.h>

#define NP 262144
#define GRIDW 256
#define NUM_CELLS (GRIDW*GRIDW)
#define KSLOT 32
#define CAP 64
#define MAXN 64

// ---------------- scratch (device globals; no allocation allowed) ----------
__device__ unsigned g_maxH;
__device__ unsigned g_minX;
__device__ unsigned g_minY;
__device__ int      g_lin[NP];
__device__ int      g_cellCount[NUM_CELLS + 1];
__device__ int      g_cellList[NUM_CELLS * CAP];
__device__ int      g_tabCnt[NUM_CELLS + 1];
__device__ float4   g_tab[(NUM_CELLS + 1) * KSLOT];   // {bits(idx), x, y, pad}

// ---------------- kernel 0: reset ------------------------------------------
__global__ void initK() {
    int i = blockIdx.x * blockDim.x + threadIdx.x;
    if (i == 0) {
        g_maxH = 0u;
        g_minX = 0x7f800000u;   // +inf (all coords >= 0, uint order == float order)
        g_minY = 0x7f800000u;
    }
    for (int c = i; c <= NUM_CELLS; c += gridDim.x * blockDim.x)
        g_cellCount[c] = 0;
}

// ---------------- kernel 1: reductions (max support, min x, min y) ---------
__global__ void reduceK(const float* __restrict__ pos, const float* __restrict__ sup) {
    __shared__ float sH[256], sX[256], sY[256];
    float h = 0.0f, x = __int_as_float(0x7f800000), y = __int_as_float(0x7f800000);
    for (int i = blockIdx.x * blockDim.x + threadIdx.x; i < NP;
         i += gridDim.x * blockDim.x) {
        h = fmaxf(h, sup[i]);
        float2 p = ((const float2*)pos)[i];
        x = fminf(x, p.x);
        y = fminf(y, p.y);
    }
    int t = threadIdx.x;
    sH[t] = h; sX[t] = x; sY[t] = y;
    __syncthreads();
    for (int s = blockDim.x / 2; s > 0; s >>= 1) {
        if (t < s) {
            sH[t] = fmaxf(sH[t], sH[t + s]);
            sX[t] = fminf(sX[t], sX[t + s]);
            sY[t] = fminf(sY[t], sY[t + s]);
        }
        __syncthreads();
    }
    if (t == 0) {
        atomicMax(&g_maxH, __float_as_uint(sH[0]));
        atomicMin(&g_minX, __float_as_uint(sX[0]));
        atomicMin(&g_minY, __float_as_uint(sY[0]));
    }
}

// ---------------- kernel 2: bin particles into cells ------------------------
__global__ void binK(const float* __restrict__ pos) {
    int i = blockIdx.x * blockDim.x + threadIdx.x;
    if (i >= NP) return;
    float h  = __uint_as_float(g_maxH);
    float qx = __uint_as_float(g_minX) - h;
    float qy = __uint_as_float(g_minY) - h;
    float2 p = ((const float2*)pos)[i];
    int ix = (int)ceilf((p.x - qx) / h);
    int iy = (int)ceilf((p.y - qy) / h);
    ix = min(max(ix, 0), GRIDW - 1);
    iy = min(max(iy, 0), GRIDW - 1);
    int lin = ix + GRIDW * iy;
    g_lin[i] = lin;
    int slot = atomicAdd(&g_cellCount[lin], 1);
    if (slot < CAP) g_cellList[lin * CAP + slot] = i;
}

// ---------------- kernel 3: per-cell index sort + packed table --------------
__global__ void sortK(const float* __restrict__ pos) {
    int c = blockIdx.x * blockDim.x + threadIdx.x;
    if (c > NUM_CELLS) return;
    int cnt = g_cellCount[c];
    int cc = min(cnt, CAP);
    int a[CAP];
    for (int s = 0; s < cc; s++) a[s] = g_cellList[c * CAP + s];
    // insertion sort ascending (stable argsort => slot order = ascending index)
    for (int s = 1; s < cc; s++) {
        int v = a[s];
        int j = s - 1;
        while (j >= 0 && a[j] > v) { a[j + 1] = a[j]; j--; }
        a[j + 1] = v;
    }
    int m = min(cc, KSLOT);
    g_tabCnt[c] = m;
    for (int s = 0; s < m; s++) {
        int idx = a[s];
        float2 p = ((const float2*)pos)[idx];
        g_tab[c * KSLOT + s] = make_float4(__int_as_float(idx), p.x, p.y, 0.0f);
    }
}

// ---------------- kernel 4: neighbor search ---------------------------------
__global__ void searchK(const float* __restrict__ pos,
                        const float* __restrict__ sup,
                        float* __restrict__ out) {
    int i = blockIdx.x * blockDim.x + threadIdx.x;
    if (i >= NP) return;
    float2 p = ((const float2*)pos)[i];
    float h  = sup[i];
    int lin  = g_lin[i];

    float* outN = out;                              // (N, 64) neighbor indices
    float* outC = out + (size_t)NP * MAXN;          // (N,)    counts
    float* outR = outC + NP;                        // (N, 64) radial

    const int offs[9] = { -GRIDW - 1, -1, GRIDW - 1,
                          -GRIDW,      0, GRIDW,
                          -GRIDW + 1,  1, GRIDW + 1 };
    size_t base = (size_t)i * MAXN;
    int cnt = 0;
#pragma unroll
    for (int o = 0; o < 9; o++) {
        int c = lin + offs[o];
        c = min(max(c, 0), NUM_CELLS);
        int m = g_tabCnt[c];
        const float4* row = &g_tab[c * KSLOT];
        for (int s = 0; s < m; s++) {
            float4 e = row[s];
            float dx = __fsub_rn(e.y, p.x);
            float dy = __fsub_rn(e.z, p.y);
            float d2 = __fadd_rn(__fmul_rn(dx, dx), __fmul_rn(dy, dy));
            float dist = __fsqrt_rn(d2);
            if (dist <= h) {
                if (cnt < MAXN) {
                    outN[base + cnt] = (float)__float_as_int(e.x);
                    outR[base + cnt] = __fdiv_rn(dist, h);
                }
                cnt++;
            }
        }
    }
    for (int k = min(cnt, MAXN); k < MAXN; k++) {
        outN[base + k] = -1.0f;
        outR[base + k] = 0.0f;
    }
    outC[i] = (float)cnt;
}

// ---------------- launch -----------------------------------------------------
extern "C" void kernel_launch(void* const* d_in, const int* in_sizes, int n_in,
                              void* d_out, int out_size) {
    const float* pos = (const float*)d_in[0];   // (N, 2) float32
    const float* sup = (const float*)d_in[1];   // (N,)   float32
    float* out = (float*)d_out;

    initK<<<256, 256>>>();
    reduceK<<<256, 256>>>(pos, sup);
    binK<<<NP / 256, 256>>>(pos);
    sortK<<<(NUM_CELLS + 1 + 255) / 256, 256>>>(pos);
    searchK<<<NP / 256, 256>>>(pos, sup, out);
}

// round 2
// speedup vs baseline: 2.4097x; 2.4097x over previous
#include <cuda_runtime.h>

#define NP 262144
#define GRIDW 256
#define NUM_CELLS (GRIDW*GRIDW)
#define KSLOT 32
#define CAP 64
#define MAXN 64
#define FULLM 0xffffffffu

// ---------------- scratch (device globals) ----------------------------------
__device__ unsigned g_maxH;
__device__ unsigned g_minX;
__device__ unsigned g_minY;
__device__ int      g_lin[NP];
__device__ int      g_cellCount[NUM_CELLS + 1];
__device__ int      g_cellList[NUM_CELLS * CAP];
__device__ int      g_tabCnt[NUM_CELLS + 1];
__device__ float4   g_tab[(NUM_CELLS + 1) * KSLOT];   // {bits(idx), x, y, pad}

// ---------------- kernel 0: reset -------------------------------------------
__global__ void initK() {
    int i = blockIdx.x * blockDim.x + threadIdx.x;
    if (i == 0) {
        g_maxH = 0u;
        g_minX = 0x7f800000u;   // +inf (coords >= 0 -> uint order == float order)
        g_minY = 0x7f800000u;
    }
    for (int c = i; c <= NUM_CELLS; c += gridDim.x * blockDim.x)
        g_cellCount[c] = 0;
}

// ---------------- kernel 1: reductions --------------------------------------
__global__ void reduceK(const float* __restrict__ pos, const float* __restrict__ sup) {
    __shared__ float sH[256], sX[256], sY[256];
    float h = 0.0f, x = __int_as_float(0x7f800000), y = __int_as_float(0x7f800000);
    for (int i = blockIdx.x * blockDim.x + threadIdx.x; i < NP;
         i += gridDim.x * blockDim.x) {
        h = fmaxf(h, sup[i]);
        float2 p = ((const float2*)pos)[i];
        x = fminf(x, p.x);
        y = fminf(y, p.y);
    }
    int t = threadIdx.x;
    sH[t] = h; sX[t] = x; sY[t] = y;
    __syncthreads();
    for (int s = blockDim.x / 2; s > 0; s >>= 1) {
        if (t < s) {
            sH[t] = fmaxf(sH[t], sH[t + s]);
            sX[t] = fminf(sX[t], sX[t + s]);
            sY[t] = fminf(sY[t], sY[t + s]);
        }
        __syncthreads();
    }
    if (t == 0) {
        atomicMax(&g_maxH, __float_as_uint(sH[0]));
        atomicMin(&g_minX, __float_as_uint(sX[0]));
        atomicMin(&g_minY, __float_as_uint(sY[0]));
    }
}

// ---------------- kernel 2: bin particles -----------------------------------
__global__ void binK(const float* __restrict__ pos) {
    int i = blockIdx.x * blockDim.x + threadIdx.x;
    if (i >= NP) return;
    float h  = __uint_as_float(g_maxH);
    float qx = __uint_as_float(g_minX) - h;
    float qy = __uint_as_float(g_minY) - h;
    float2 p = ((const float2*)pos)[i];
    int ix = (int)ceilf((p.x - qx) / h);
    int iy = (int)ceilf((p.y - qy) / h);
    ix = min(max(ix, 0), GRIDW - 1);
    iy = min(max(iy, 0), GRIDW - 1);
    int lin = ix + GRIDW * iy;
    g_lin[i] = lin;
    int slot = atomicAdd(&g_cellCount[lin], 1);
    if (slot < CAP) g_cellList[lin * CAP + slot] = i;
}

// ---------------- kernel 3: warp-per-cell rank sort + packed table ----------
__global__ void sortK(const float* __restrict__ pos) {
    int w = (blockIdx.x * blockDim.x + threadIdx.x) >> 5;
    if (w > NUM_CELLS) return;
    int lane = threadIdx.x & 31;
    int cnt = g_cellCount[w];
    int m = min(cnt, KSLOT);
    int idx = (lane < m) ? g_cellList[w * CAP + lane] : 0x7fffffff;
    // rank = number of smaller indices among the m entries (indices distinct)
    int rank = 0;
    for (int j = 0; j < m; j++) {
        int v = __shfl_sync(FULLM, idx, j);
        rank += (v < idx);
    }
    if (lane == 0) g_tabCnt[w] = m;
    if (lane < m) {
        float2 p = ((const float2*)pos)[idx];
        g_tab[w * KSLOT + rank] = make_float4(__int_as_float(idx), p.x, p.y, 0.0f);
    }
}

// ---------------- kernel 4: warp-per-particle neighbor search ---------------
__global__ void searchK(const float* __restrict__ pos,
                        const float* __restrict__ sup,
                        float* __restrict__ out) {
    int gw = (blockIdx.x * blockDim.x + threadIdx.x) >> 5;   // warp id = particle
    if (gw >= NP) return;
    int lane = threadIdx.x & 31;

    float2 p = ((const float2*)pos)[gw];
    float h  = sup[gw];
    int lin  = g_lin[gw];

    // lanes 0..8 own the 9 stencil cells (same order as reference offs)
    int c = NUM_CELLS, m = 0;
    if (lane < 9) {
        int dxo = lane / 3 - 1;
        int dyo = lane % 3 - 1;
        int cc = lin + dxo + GRIDW * dyo;
        cc = min(max(cc, 0), NUM_CELLS);
        c = cc;
        m = g_tabCnt[cc];
    }
    // inclusive scan of m over lanes
    int incl = m;
#pragma unroll
    for (int d = 1; d < 32; d <<= 1) {
        int v = __shfl_up_sync(FULLM, incl, d);
        if (lane >= d) incl += v;
    }
    int pref = incl - m;                      // exclusive prefix
    int T = __shfl_sync(FULLM, incl, 8);      // total candidates

    // broadcast prefixes (constant-indexed registers)
    int p1 = __shfl_sync(FULLM, pref, 1);
    int p2 = __shfl_sync(FULLM, pref, 2);
    int p3 = __shfl_sync(FULLM, pref, 3);
    int p4 = __shfl_sync(FULLM, pref, 4);
    int p5 = __shfl_sync(FULLM, pref, 5);
    int p6 = __shfl_sync(FULLM, pref, 6);
    int p7 = __shfl_sync(FULLM, pref, 7);
    int p8 = __shfl_sync(FULLM, pref, 8);

    float* outN = out;                              // (N, 64) neighbor indices
    float* outC = out + (size_t)NP * MAXN;          // (N,)    counts
    float* outR = outC + NP;                        // (N, 64) radial
    size_t base = (size_t)gw * MAXN;

    int cnt = 0;
    for (int tb = 0; tb < T; tb += 32) {
        int t = tb + lane;
        bool act = t < T;
        // which stencil cell does candidate t fall in?
        int o = (t >= p1) + (t >= p2) + (t >= p3) + (t >= p4) +
                (t >= p5) + (t >= p6) + (t >= p7) + (t >= p8);
        int cc = __shfl_sync(FULLM, c, o);
        int po = __shfl_sync(FULLM, pref, o);
        int s  = t - po;

        float nidx = 0.0f, dist = 0.0f;
        bool ok = false;
        if (act) {
            float4 e = g_tab[cc * KSLOT + s];
            float dx = __fsub_rn(e.y, p.x);
            float dy = __fsub_rn(e.z, p.y);
            float d2 = __fadd_rn(__fmul_rn(dx, dx), __fmul_rn(dy, dy));
            dist = __fsqrt_rn(d2);
            nidx = (float)__float_as_int(e.x);
            ok = (dist <= h);
        }
        unsigned bal = __ballot_sync(FULLM, ok);
        int slot = cnt + __popc(bal & ((1u << lane) - 1u));
        if (ok && slot < MAXN) {
            outN[base + slot] = nidx;
            outR[base + slot] = __fdiv_rn(dist, h);
        }
        cnt += __popc(bal);
    }
    // fill the tail
    int start = min(cnt, MAXN);
    for (int k = start + lane; k < MAXN; k += 32) {
        outN[base + k] = -1.0f;
        outR[base + k] = 0.0f;
    }
    if (lane == 0) outC[gw] = (float)cnt;
}

// ---------------- launch ------------------------------------------------------
extern "C" void kernel_launch(void* const* d_in, const int* in_sizes, int n_in,
                              void* d_out, int out_size) {
    const float* pos = (const float*)d_in[0];   // (N, 2) float32
    const float* sup = (const float*)d_in[1];   // (N,)   float32
    float* out = (float*)d_out;

    initK<<<256, 256>>>();
    reduceK<<<256, 256>>>(pos, sup);
    binK<<<NP / 256, 256>>>(pos);
    sortK<<<((NUM_CELLS + 1) * 32 + 255) / 256, 256>>>(pos);
    searchK<<<(NP * 32) / 256, 256>>>(pos, sup, out);
}